// round 3
// baseline (speedup 1.0000x reference)
#include <cuda_runtime.h>
#include <cstdint>

#define S   512
#define BB  64
#define TT  512
#define VV  2048
#define CL  8      // CTAs per cluster
#define JC  64     // columns (next-states) per CTA
#define NB  4      // batches per cluster
#define NTHREADS 256

// Scratch (no runtime allocation allowed)
__device__ float g_T[S * S];        // row-softmax of trans_logits, row-major [i][j]
__device__ float g_logEt[VV * S];   // log_softmax(emit) transposed: [v][s]

// ---------------- cluster helpers ----------------
__device__ __forceinline__ unsigned cluster_rank() {
    unsigned r; asm("mov.u32 %0, %%cluster_ctarank;" : "=r"(r)); return r;
}
__device__ __forceinline__ void cluster_sync_all() {
    asm volatile("barrier.cluster.arrive.aligned;" ::: "memory");
    asm volatile("barrier.cluster.wait.aligned;" ::: "memory");
}
__device__ __forceinline__ float dsmem_ld(const float* p, unsigned rank) {
    unsigned a = (unsigned)__cvta_generic_to_shared((void*)p);
    unsigned ra;
    asm("mapa.shared::cluster.u32 %0, %1, %2;" : "=r"(ra) : "r"(a), "r"(rank));
    float v;
    asm volatile("ld.shared::cluster.f32 %0, [%1];" : "=f"(v) : "r"(ra) : "memory");
    return v;
}

// ---------------- block reduce (256 threads / 8 warps) ----------------
template <bool IS_MAX>
__device__ __forceinline__ float blk_reduce(float v, float* scratch) {
    #pragma unroll
    for (int o = 16; o; o >>= 1) {
        float w = __shfl_xor_sync(~0u, v, o);
        v = IS_MAX ? fmaxf(v, w) : v + w;
    }
    int warp = threadIdx.x >> 5, lane = threadIdx.x & 31;
    if (lane == 0) scratch[warp] = v;
    __syncthreads();
    if (threadIdx.x < 8) {
        v = scratch[threadIdx.x];
        #pragma unroll
        for (int o = 4; o; o >>= 1) {
            float w = __shfl_xor_sync(0xffu, v, o);
            v = IS_MAX ? fmaxf(v, w) : v + w;
        }
        if (threadIdx.x == 0) scratch[0] = v;
    }
    __syncthreads();
    v = scratch[0];
    __syncthreads();
    return v;
}

// ---------------- prep: T = softmax(trans_logits, axis=-1) ----------------
__global__ void prep_trans(const float* __restrict__ trans) {
    __shared__ float scratch[8];
    const int row = blockIdx.x;
    const float* x = trans + row * S;
    const int tid = threadIdx.x;

    float m = -1e30f;
    for (int i = tid; i < S; i += NTHREADS) m = fmaxf(m, x[i]);
    m = blk_reduce<true>(m, scratch);

    float s = 0.f;
    for (int i = tid; i < S; i += NTHREADS) s += __expf(x[i] - m);
    s = blk_reduce<false>(s, scratch);

    const float inv = 1.0f / s;
    for (int i = tid; i < S; i += NTHREADS)
        g_T[row * S + i] = __expf(x[i] - m) * inv;
}

// ---------------- prep: logEt[v][s] = log_softmax(emit[s,:])[v] ----------------
__global__ void prep_emit(const float* __restrict__ emit) {
    __shared__ float scratch[8];
    const int row = blockIdx.x;          // state s
    const float* x = emit + row * VV;
    const int tid = threadIdx.x;

    float m = -1e30f;
    for (int i = tid; i < VV; i += NTHREADS) m = fmaxf(m, x[i]);
    m = blk_reduce<true>(m, scratch);

    float s = 0.f;
    for (int i = tid; i < VV; i += NTHREADS) s += __expf(x[i] - m);
    s = blk_reduce<false>(s, scratch);

    const float lse = m + __logf(s);
    for (int i = tid; i < VV; i += NTHREADS)
        g_logEt[i * S + row] = x[i] - lse;
}

// ---------------- main: persistent clustered forward scan ----------------
// grid = 128 CTAs (16 clusters of 8). Cluster c owns batches [4c, 4c+4).
// CTA rank r owns columns [64r, 64r+64) and its 128KB T slice in smem.
__global__ void __cluster_dims__(CL, 1, 1) __launch_bounds__(NTHREADS, 1)
hmm_main(const int* __restrict__ value, const float* __restrict__ prior,
         float* __restrict__ out) {
    extern __shared__ float sm[];
    float* T_s   = sm;                    // S*JC       = 32768
    float* p_s   = T_s + S * JC;          // NB*S       = 2048
    float* vbuf  = p_s + NB * S;          // 2*NB*JC    = 512   (double-buffered)
    float* mbuf  = vbuf + 2 * NB * JC;    // 2*NB       = 8     (double-buffered)
    float* red   = mbuf + 2 * NB;         // 16*NB*JC   = 4096  (GEMV partials)
    float* wmaxb = red + 16 * NB * JC;    // 8
    float* m_s   = wmaxb + 8;             // NB
    float* c_s   = m_s + NB;              // NB
    float* lpl   = c_s + NB;              // 1

    const unsigned r = cluster_rank();
    const int clus  = blockIdx.x >> 3;
    const int b0    = clus * NB;
    const int jbase = (int)r * JC;
    const int tid   = threadIdx.x;
    const int b     = tid >> 6;           // batch slot 0..3
    const int j     = tid & 63;           // local column
    const int warp  = tid >> 5;
    const int lane  = tid & 31;
    const int jq    = tid & 15;           // column quad for GEMV
    const int ip    = tid >> 4;           // i-partition (16 x 32 rows)

    // Load this CTA's T column slice: T_s[i*64 + jj] = T[i][jbase+jj]
    for (int idx = tid; idx < S * JC; idx += NTHREADS) {
        int i  = idx >> 6;
        int jj = idx & 63;
        T_s[idx] = g_T[i * S + jbase + jj];
    }

    // prior logsumexp (redundant per CTA, trivial)
    {
        float m = -1e30f;
        for (int i = tid; i < S; i += NTHREADS) m = fmaxf(m, prior[i]);
        m = blk_reduce<true>(m, wmaxb);
        float s = 0.f;
        for (int i = tid; i < S; i += NTHREADS) s += __expf(prior[i] - m);
        s = blk_reduce<false>(s, wmaxb);
        if (tid == 0) lpl[0] = m + __logf(s);
        if (tid < NB) c_s[tid] = 0.f;
        __syncthreads();
    }
    const float lp_lse = lpl[0];

    int bufsel = 0;

    #pragma unroll 1
    for (int t = 0; t < TT; ++t) {
        // emission for this thread's (b, j) — issued early to hide latency
        const int obs = value[(b0 + b) * TT + t];
        const float em = g_logEt[obs * S + jbase + j];

        float vv;
        if (t == 0) {
            vv = em + prior[jbase + j] - lp_lse;
        } else {
            // GEMV slice: q[b][j] = sum_i p[b][i] * T_s[i][j]
            float4 a0 = {0,0,0,0}, a1 = {0,0,0,0}, a2 = {0,0,0,0}, a3 = {0,0,0,0};
            const float4* T4 = (const float4*)T_s;
            const int ibeg = ip * 32;
            #pragma unroll 8
            for (int i = ibeg; i < ibeg + 32; ++i) {
                float4 tv = T4[i * 16 + jq];
                float q0 = p_s[i];
                float q1 = p_s[S + i];
                float q2 = p_s[2 * S + i];
                float q3 = p_s[3 * S + i];
                a0.x += q0 * tv.x; a0.y += q0 * tv.y; a0.z += q0 * tv.z; a0.w += q0 * tv.w;
                a1.x += q1 * tv.x; a1.y += q1 * tv.y; a1.z += q1 * tv.z; a1.w += q1 * tv.w;
                a2.x += q2 * tv.x; a2.y += q2 * tv.y; a2.z += q2 * tv.z; a2.w += q2 * tv.w;
                a3.x += q3 * tv.x; a3.y += q3 * tv.y; a3.z += q3 * tv.z; a3.w += q3 * tv.w;
            }
            float4* R4 = (float4*)red;
            R4[(ip * NB + 0) * 16 + jq] = a0;
            R4[(ip * NB + 1) * 16 + jq] = a1;
            R4[(ip * NB + 2) * 16 + jq] = a2;
            R4[(ip * NB + 3) * 16 + jq] = a3;
            __syncthreads();
            float q = 0.f;
            #pragma unroll
            for (int k = 0; k < 16; ++k) q += red[(k * NB + b) * JC + j];
            vv = em + __logf(q);
        }

        // publish v slice + local max for the cluster exchange
        vbuf[bufsel * NB * JC + tid] = vv;
        float wm = vv;
        #pragma unroll
        for (int o = 16; o; o >>= 1) wm = fmaxf(wm, __shfl_xor_sync(~0u, wm, o));
        if (lane == 0) wmaxb[warp] = wm;
        __syncthreads();
        if (tid < NB) {
            float lm = fmaxf(wmaxb[2 * tid], wmaxb[2 * tid + 1]);
            mbuf[bufsel * NB + tid] = lm;
        }

        cluster_sync_all();

        // global max per batch (across 8 ranks), update running constant
        if (tid < NB) {
            float gm = -1e30f;
            #pragma unroll
            for (int rr = 0; rr < CL; ++rr)
                gm = fmaxf(gm, dsmem_ld(&mbuf[bufsel * NB + tid], rr));
            m_s[tid] = gm;
            c_s[tid] += gm;
        }
        __syncthreads();

        // rebuild full normalized p[b][0..511] locally from peer v slices
        for (int idx = tid; idx < NB * S; idx += NTHREADS) {
            int bb = idx >> 9;
            int i  = idx & 511;
            int rr = i >> 6;
            int jj = i & 63;
            float pv = dsmem_ld(&vbuf[bufsel * NB * JC + bb * JC + jj], (unsigned)rr);
            p_s[idx] = __expf(pv - m_s[bb]);
        }
        __syncthreads();
        bufsel ^= 1;
    }

    cluster_sync_all();   // keep peer smem alive until everyone is done reading

    // answer[b] = C[b] + log(sum_i p[b][i]); every CTA has identical p/C — rank 0 writes
    if (r == 0) {
        for (int bb = 0; bb < NB; ++bb) {
            float s = 0.f;
            for (int i = tid; i < S; i += NTHREADS) s += p_s[bb * S + i];
            s = blk_reduce<false>(s, wmaxb);
            if (tid == 0) out[b0 + bb] = c_s[bb] + __logf(s);
        }
    }
}

static const int SMEM_BYTES =
    (S * JC + NB * S + 2 * NB * JC + 2 * NB + 16 * NB * JC + 8 + NB + NB + 4) * 4;

extern "C" void kernel_launch(void* const* d_in, const int* in_sizes, int n_in,
                              void* d_out, int out_size) {
    (void)in_sizes; (void)n_in; (void)out_size;
    const int*   value = (const int*)d_in[0];
    const float* prior = (const float*)d_in[1];
    const float* trans = (const float*)d_in[2];
    const float* emit  = (const float*)d_in[3];
    float* out = (float*)d_out;

    prep_trans<<<S, NTHREADS>>>(trans);
    prep_emit<<<S, NTHREADS>>>(emit);

    cudaFuncSetAttribute(hmm_main, cudaFuncAttributeMaxDynamicSharedMemorySize, SMEM_BYTES);
    hmm_main<<<(BB / NB) * CL, NTHREADS, SMEM_BYTES>>>(value, prior, out);
}

// round 4
// speedup vs baseline: 1.5737x; 1.5737x over previous
#include <cuda_runtime.h>
#include <cstdint>

#define S    512
#define TT   512
#define VV   2048
#define CL   8      // CTAs per cluster
#define JC   64     // columns (next-states) per CTA
#define NB   4      // batches per cluster
#define NT   512    // threads per CTA
#define PPAD 520    // padded p row stride (banks differ per batch row)

// float offsets inside dynamic smem
#define T_OFF   0
#define P_OFF   (S*JC)                    // 32768, 2 buffers of NB*PPAD
#define S_OFF   (P_OFF + 2*NB*PPAD)       // 36928, s_slot[2][NB]
#define RED_OFF (S_OFF + 2*NB)            // 36936, 16*NB*64 partials
#define SCR_OFF (RED_OFF + 16*NB*JC)      // 41032, reduce scratch (16)
#define C_OFF   (SCR_OFF + 16)            // 41048, running C[NB]
#define VAL_OFF (C_OFF + NB)              // 41052, value cache NB*TT ints
#define SMEM_FLOATS (VAL_OFF + NB*TT)     // 43100 floats = 172400 B

__device__ float g_T[S * S];        // row-softmax of trans_logits  [i][j]
__device__ float g_logEt[VV * S];   // log_softmax(emit) transposed [v][s]

// ---------------- cluster helpers ----------------
__device__ __forceinline__ unsigned cluster_rank() {
    unsigned r; asm("mov.u32 %0, %%cluster_ctarank;" : "=r"(r)); return r;
}
__device__ __forceinline__ void cluster_sync_all() {
    asm volatile("barrier.cluster.arrive.aligned;" ::: "memory");
    asm volatile("barrier.cluster.wait.aligned;" ::: "memory");
}

// ---------------- block reduce ----------------
template <int NW, bool MX>
__device__ __forceinline__ float blk_red(float v, float* scr) {
    #pragma unroll
    for (int o = 16; o; o >>= 1) {
        float w = __shfl_xor_sync(~0u, v, o);
        v = MX ? fmaxf(v, w) : v + w;
    }
    int wp = threadIdx.x >> 5, ln = threadIdx.x & 31;
    if (ln == 0) scr[wp] = v;
    __syncthreads();
    if ((int)threadIdx.x < NW) {
        v = scr[threadIdx.x];
        #pragma unroll
        for (int o = NW / 2; o; o >>= 1) {
            float w = __shfl_xor_sync((1u << NW) - 1u, v, o);
            v = MX ? fmaxf(v, w) : v + w;
        }
        if (threadIdx.x == 0) scr[0] = v;
    }
    __syncthreads();
    v = scr[0];
    __syncthreads();
    return v;
}

// ---------------- prep: T = softmax(trans_logits, axis=-1) ----------------
__global__ void prep_trans(const float* __restrict__ trans) {
    __shared__ float scratch[8];
    const int row = blockIdx.x;
    const float* x = trans + row * S;
    const int tid = threadIdx.x;

    float m = -1e30f;
    for (int i = tid; i < S; i += 256) m = fmaxf(m, x[i]);
    m = blk_red<8, true>(m, scratch);

    float s = 0.f;
    for (int i = tid; i < S; i += 256) s += __expf(x[i] - m);
    s = blk_red<8, false>(s, scratch);

    const float inv = 1.0f / s;
    for (int i = tid; i < S; i += 256)
        g_T[row * S + i] = __expf(x[i] - m) * inv;
}

// ---------------- prep: logEt[v][s] = log_softmax(emit[s,:])[v] ----------------
__global__ void prep_emit(const float* __restrict__ emit) {
    __shared__ float scratch[8];
    const int row = blockIdx.x;          // state s
    const float* x = emit + row * VV;
    const int tid = threadIdx.x;

    float m = -1e30f;
    for (int i = tid; i < VV; i += 256) m = fmaxf(m, x[i]);
    m = blk_red<8, true>(m, scratch);

    float s = 0.f;
    for (int i = tid; i < VV; i += 256) s += __expf(x[i] - m);
    s = blk_red<8, false>(s, scratch);

    const float lse = m + __logf(s);
    for (int i = tid; i < VV; i += 256)
        g_logEt[i * S + row] = x[i] - lse;
}

// ---------------- main: persistent clustered forward scan ----------------
// 16 clusters x 8 CTAs. Cluster c owns batches [4c,4c+4); rank r owns cols [64r,64r+64).
// Per step: conflict-free smem GEMV -> v = em + log q -> p = exp(v - s_lag) pushed
// to all 8 ranks via st.shared::cluster; one cluster barrier per step.
__global__ void __cluster_dims__(CL, 1, 1) __launch_bounds__(NT, 1)
hmm_main(const int* __restrict__ value, const float* __restrict__ prior,
         float* __restrict__ out) {
    extern __shared__ float sm[];
    float* T_s  = sm + T_OFF;
    float* p_s  = sm + P_OFF;
    float* s_sl = sm + S_OFF;
    float* red  = sm + RED_OFF;
    float* scr  = sm + SCR_OFF;
    float* c_s  = sm + C_OFF;
    int*   vch  = (int*)(sm + VAL_OFF);

    const unsigned rank = cluster_rank();
    const int clus  = blockIdx.x >> 3;
    const int b0    = clus * NB;
    const int jbase = (int)rank * JC;
    const int tid   = threadIdx.x;
    const int lane  = tid & 31;
    const int w     = tid >> 5;     // 16 warps
    const int jq    = lane & 15;    // j quad (cols 4jq..4jq+3)
    const int bh    = lane >> 4;    // batch half: {0,1}->(b0,b1) / (b2,b3)

    // Load this CTA's T column slice: T_s[i*64 + jj] = T[i][jbase+jj]
    for (int idx = tid; idx < S * JC; idx += NT) {
        int i = idx >> 6, jj = idx & 63;
        T_s[idx] = g_T[i * S + jbase + jj];
    }
    if (tid < 2 * NB) s_sl[tid] = 0.f;
    if (tid < NB)     c_s[tid] = 0.f;
    // cache observation rows
    for (int idx = tid; idx < NB * TT; idx += NT) {
        int bb = idx >> 9, t = idx & 511;
        vch[idx] = value[(b0 + bb) * TT + t];
    }

    // prior logsumexp
    float m = -1e30f;
    for (int i = tid; i < S; i += NT) m = fmaxf(m, prior[i]);
    m = blk_red<16, true>(m, scr);
    float ss = 0.f;
    for (int i = tid; i < S; i += NT) ss += __expf(prior[i] - m);
    ss = blk_red<16, false>(ss, scr);
    const float lp_lse = m + __logf(ss);

    __syncthreads();
    cluster_sync_all();    // peers' s_slot/vcache init done before any push

    // remote smem window bases (mapa is offset-preserving within a CTA window)
    unsigned base_u = (unsigned)__cvta_generic_to_shared((void*)sm);
    unsigned rb[CL];
    #pragma unroll
    for (int r = 0; r < CL; ++r)
        asm("mapa.shared::cluster.u32 %0, %1, %2;" : "=r"(rb[r]) : "r"(base_u), "r"((unsigned)r));

    const int b = tid >> 6;   // batch (valid for tid<256)
    const int j = tid & 63;   // local column

    // ---- t = 0 ----
    if (tid < 256) {
        int obs  = vch[b * TT + 0];
        float em = __ldg(&g_logEt[obs * S + jbase + j]);
        float vv = em + __ldg(&prior[jbase + j]) - lp_lse;
        float pv = __expf(vv);                       // s_0 = 0
        unsigned off = 4u * (P_OFF + 1 * NB * PPAD + b * PPAD + jbase + j);
        #pragma unroll
        for (int r = 0; r < CL; ++r)
            asm volatile("st.shared::cluster.f32 [%0], %1;" :: "r"(rb[r] + off), "f"(pv) : "memory");
        if (rank == 0 && j == 0) {
            unsigned soff = 4u * (S_OFF + 1 * NB + b);
            #pragma unroll
            for (int r = 0; r < CL; ++r)
                asm volatile("st.shared::cluster.f32 [%0], %1;" :: "r"(rb[r] + soff), "f"(vv) : "memory");
        }
    }
    cluster_sync_all();

    #pragma unroll 1
    for (int t = 1; t < TT; ++t) {
        const int cur = t & 1, nxt = cur ^ 1;

        int obs = 0; float em = 0.f;
        if (tid < 256) {                       // prefetch; consumed after GEMV
            obs = vch[b * TT + t];
            em  = __ldg(&g_logEt[obs * S + jbase + j]);
        }

        // ---- GEMV slice: warp w covers rows [32w,32w+32), lanes cover 64 cols x 2 batch halves
        const float* pc = p_s + cur * NB * PPAD;
        const float* pA = pc + (2 * bh) * PPAD;
        const float* pB = pc + (2 * bh + 1) * PPAD;
        const float4* T4 = (const float4*)T_s;
        float4 accA = make_float4(0.f, 0.f, 0.f, 0.f);
        float4 accB = make_float4(0.f, 0.f, 0.f, 0.f);
        const int ibeg = w * 32;
        #pragma unroll
        for (int i = ibeg; i < ibeg + 32; i += 2) {
            float4 t0 = T4[i * 16 + jq];
            float4 t1 = T4[(i + 1) * 16 + jq];
            float2 a  = *(const float2*)(pA + i);
            float2 c2 = *(const float2*)(pB + i);
            accA.x = fmaf(a.y,  t1.x, fmaf(a.x,  t0.x, accA.x));
            accA.y = fmaf(a.y,  t1.y, fmaf(a.x,  t0.y, accA.y));
            accA.z = fmaf(a.y,  t1.z, fmaf(a.x,  t0.z, accA.z));
            accA.w = fmaf(a.y,  t1.w, fmaf(a.x,  t0.w, accA.w));
            accB.x = fmaf(c2.y, t1.x, fmaf(c2.x, t0.x, accB.x));
            accB.y = fmaf(c2.y, t1.y, fmaf(c2.x, t0.y, accB.y));
            accB.z = fmaf(c2.y, t1.z, fmaf(c2.x, t0.z, accB.z));
            accB.w = fmaf(c2.y, t1.w, fmaf(c2.x, t0.w, accB.w));
        }
        float4* R4 = (float4*)red;
        R4[(w * 4 + 2 * bh) * 16 + jq]     = accA;
        R4[(w * 4 + 2 * bh + 1) * 16 + jq] = accB;
        __syncthreads();

        if (tid < 256) {
            float q = 0.f;
            #pragma unroll
            for (int k = 0; k < 16; ++k) q += red[(k * 4 + b) * 64 + j];

            float s_cur = s_sl[cur * NB + b];          // lagged normalizer
            float vv = em + __logf(q);
            float pv = __expf(vv - s_cur);

            unsigned off = 4u * (P_OFF + nxt * NB * PPAD + b * PPAD + jbase + j);
            #pragma unroll
            for (int r = 0; r < CL; ++r)
                asm volatile("st.shared::cluster.f32 [%0], %1;" :: "r"(rb[r] + off), "f"(pv) : "memory");
            if (rank == 0 && j == 0) {
                unsigned soff = 4u * (S_OFF + nxt * NB + b);
                #pragma unroll
                for (int r = 0; r < CL; ++r)
                    asm volatile("st.shared::cluster.f32 [%0], %1;" :: "r"(rb[r] + soff), "f"(vv) : "memory");
            }
            if (tid < NB) c_s[tid] += s_sl[cur * NB + tid];
        }
        cluster_sync_all();   // release own pushes / acquire peers'
    }

    // final p lives in buffer 0 (TT even); every CTA has full copy + identical C
    if (rank == 0) {
        for (int bb = 0; bb < NB; ++bb) {
            float sum = 0.f;
            for (int i = tid; i < S; i += NT) sum += p_s[bb * PPAD + i];
            sum = blk_red<16, false>(sum, scr);
            if (tid == 0) out[b0 + bb] = c_s[bb] + __logf(sum);
        }
    }
}

extern "C" void kernel_launch(void* const* d_in, const int* in_sizes, int n_in,
                              void* d_out, int out_size) {
    (void)in_sizes; (void)n_in; (void)out_size;
    const int*   value = (const int*)d_in[0];
    const float* prior = (const float*)d_in[1];
    const float* trans = (const float*)d_in[2];
    const float* emit  = (const float*)d_in[3];
    float* out = (float*)d_out;

    prep_trans<<<S, 256>>>(trans);
    prep_emit<<<S, 256>>>(emit);

    cudaFuncSetAttribute(hmm_main, cudaFuncAttributeMaxDynamicSharedMemorySize,
                         SMEM_FLOATS * (int)sizeof(float));
    hmm_main<<<(64 / NB) * CL, NT, SMEM_FLOATS * sizeof(float)>>>(value, prior, out);
}